// round 7
// baseline (speedup 1.0000x reference)
#include <cuda_runtime.h>

#define BB 64
#define TT 577
#define DD 768
#define DENS 519      // int(577*0.9)
#define NSKIP 58      // 577 - 519
#define D4 (DD/4)     // 192 float4 per row
#define RPB 8         // source rows per scatter block

#define SBATCH 32                 // batches per stripe
#define NSTRIPE (BB/SBATCH)       // 2
#define SROWS (SBATCH*TT)         // 18464 rows per stripe
#define SPAIRS (SROWS/2)          // 9232
#define SSCAT (SROWS/RPB)         // 2308

// Scratch (no device allocation allowed)
__device__ float g_logits[BB*TT];
__device__ int   g_rank[BB*TT];
__device__ int   g_skip[BB*NSKIP];
__device__ float g_weights[BB*NSKIP];

// ---------------- Kernel 1: logits for one stripe (2 rows per warp) ----------------
__global__ void logits_kernel(const float* __restrict__ x,
                              const float* __restrict__ w,
                              const float* __restrict__ bias,
                              int rowOff) {
    int warpsPerBlock = blockDim.x >> 5;
    int warpId = threadIdx.x >> 5;
    int lane   = threadIdx.x & 31;
    int pair = blockIdx.x * warpsPerBlock + warpId;
    if (pair >= SPAIRS) return;
    int row0 = rowOff + pair * 2;

    const float4* xr0 = reinterpret_cast<const float4*>(x) + (size_t)row0 * D4;
    const float4* xr1 = xr0 + D4;
    const float4* w4  = reinterpret_cast<const float4*>(w);

    float4 a0[6], a1[6], wv[6];
    #pragma unroll
    for (int k = 0; k < 6; k++) a0[k] = xr0[k*32 + lane];
    #pragma unroll
    for (int k = 0; k < 6; k++) a1[k] = xr1[k*32 + lane];
    #pragma unroll
    for (int k = 0; k < 6; k++) wv[k] = __ldg(&w4[k*32 + lane]);

    float acc0 = 0.f, acc1 = 0.f;
    #pragma unroll
    for (int k = 0; k < 6; k++) {
        acc0 = fmaf(a0[k].x, wv[k].x, acc0);
        acc0 = fmaf(a0[k].y, wv[k].y, acc0);
        acc0 = fmaf(a0[k].z, wv[k].z, acc0);
        acc0 = fmaf(a0[k].w, wv[k].w, acc0);
        acc1 = fmaf(a1[k].x, wv[k].x, acc1);
        acc1 = fmaf(a1[k].y, wv[k].y, acc1);
        acc1 = fmaf(a1[k].z, wv[k].z, acc1);
        acc1 = fmaf(a1[k].w, wv[k].w, acc1);
    }
    #pragma unroll
    for (int off = 16; off; off >>= 1) {
        acc0 += __shfl_xor_sync(0xffffffffu, acc0, off);
        acc1 += __shfl_xor_sync(0xffffffffu, acc1, off);
    }
    if (lane == 0) {
        float bv = bias[0];
        g_logits[row0]     = acc0 + bv;
        g_logits[row0 + 1] = acc1 + bv;
    }
}

// ---------------- Kernel 2: rank (stable) + skip softmax, one stripe ----------------
__global__ void rank_kernel(int batchOff) {
    __shared__ float s[TT];
    __shared__ float skipP[NSKIP];
    __shared__ float skipE[NSKIP];

    int b = batchOff + blockIdx.x;
    int i = threadIdx.x;

    if (i < TT) s[i] = g_logits[b*TT + i];
    __syncthreads();

    if (i < TT) {
        float my = s[i];
        int rank = 0;
        #pragma unroll 8
        for (int j = 0; j < TT; j++) {
            float v = s[j];
            rank += (v > my) || (v == my && j < i);   // stable: lower index wins
        }
        g_rank[b*TT + i] = rank;
        if (rank >= DENS) {
            int pos = (TT - 1) - rank;                // ascending skipped order
            g_skip[b*NSKIP + pos] = i;
            skipP[pos] = 1.f / (1.f + expf(-my));     // sigmoid prob
        }
    }
    __syncthreads();

    if (i < NSKIP) {
        float m = -1e30f;
        #pragma unroll
        for (int j = 0; j < NSKIP; j++) m = fmaxf(m, skipP[j]);
        skipE[i] = expf(skipP[i] - m);
    }
    __syncthreads();

    if (i < NSKIP) {
        float sum = 0.f;
        #pragma unroll
        for (int j = 0; j < NSKIP; j++) sum += skipE[j];
        g_weights[b*NSKIP + i] = skipE[i] / sum;
    }
}

// ---------------- Kernel 3: fused scatter + summary, one stripe ----------------
// Blocks [0, SBATCH)              : summary for batch batchOff+blockIdx (hidden under scatter)
// Blocks [SBATCH, SBATCH+SSCAT)   : scatter RPB sequential rows of this stripe
__global__ void scatter_summary_kernel(const float* __restrict__ x,
                                       float* __restrict__ out,
                                       int batchOff) {
    const float4* xin = reinterpret_cast<const float4*>(x);
    float4* o4 = reinterpret_cast<float4*>(out);
    const size_t skipBase = (size_t)BB * DENS * D4;
    const size_t sumBase  = (size_t)BB * (DENS + NSKIP) * D4;
    int tid = threadIdx.x;              // 0..191

    if (blockIdx.x < SBATCH) {
        // ---- summary path (reads this stripe's rows: L2 hits) ----
        __shared__ int   sidx[NSKIP];
        __shared__ float swgt[NSKIP];
        int b = batchOff + blockIdx.x;
        if (tid < NSKIP) {
            sidx[tid] = g_skip[b*NSKIP + tid];
            swgt[tid] = g_weights[b*NSKIP + tid];
        }
        __syncthreads();

        float4 acc = make_float4(0.f, 0.f, 0.f, 0.f);
        #pragma unroll 2
        for (int sI = 0; sI < NSKIP; sI++) {
            int src = sidx[sI];
            float wgt = swgt[sI];
            float4 vv = xin[((size_t)b*TT + src) * D4 + tid];
            acc.x = fmaf(wgt, vv.x, acc.x);
            acc.y = fmaf(wgt, vv.y, acc.y);
            acc.z = fmaf(wgt, vv.z, acc.z);
            acc.w = fmaf(wgt, vv.w, acc.w);
        }
        o4[sumBase + (size_t)b * D4 + tid] = acc;
    } else {
        // ---- scatter path: reads stripe rows just warmed into L2 by logits ----
        int base = batchOff*TT + (blockIdx.x - SBATCH) * RPB;

        // Front-batched independent loads (MLP=8); evict-first after single use
        float4 v[RPB];
        #pragma unroll
        for (int r = 0; r < RPB; r++)
            v[r] = __ldcs(&xin[((size_t)(base + r)) * D4 + tid]);

        #pragma unroll
        for (int r = 0; r < RPB; r++) {
            int src = base + r;
            int b = src / TT;
            int rank = g_rank[src];
            size_t off = (rank < DENS)
                ? ((size_t)(b*DENS + rank) * D4)
                : (skipBase + (size_t)(b*NSKIP + ((TT-1) - rank)) * D4);
            // streaming store: evict-first, protect the resident x stripe in L2
            __stcs(&o4[off + tid], v[r]);
        }
    }
}

extern "C" void kernel_launch(void* const* d_in, const int* in_sizes, int n_in,
                              void* d_out, int out_size) {
    const float* x    = (const float*)d_in[0];
    const float* w    = (const float*)d_in[1];
    const float* bias = (const float*)d_in[2];
    float* out = (float*)d_out;

    for (int s = 0; s < NSTRIPE; s++) {
        int batchOff = s * SBATCH;
        int rowOff   = batchOff * TT;
        // 1) logits for stripe: 2 rows/warp, 8 warps/block
        logits_kernel<<<(SPAIRS + 7) / 8, 256>>>(x, w, bias, rowOff);
        // 2) rank + softmax for stripe
        rank_kernel<<<SBATCH, 608>>>(batchOff);
        // 3) scatter + summaries for stripe (reads hit L2-resident stripe)
        scatter_summary_kernel<<<SBATCH + SSCAT, 192>>>(x, out, batchOff);
    }
}

// round 8
// speedup vs baseline: 1.3031x; 1.3031x over previous
#include <cuda_runtime.h>

#define BB 64
#define TT 577
#define DD 768
#define DENS 519      // int(577*0.9)
#define NSKIP 58      // 577 - 519
#define D4 (DD/4)     // 192 float4 per row
#define RPB 8         // source rows per scatter block
#define NROWS (BB*TT) // 36928
#define NSCAT (NROWS/RPB) // 4616
#define NTHR 192

// Scratch (no device allocation allowed)
__device__ float g_logits[NROWS];
__device__ int   g_rank[NROWS];
__device__ int   g_flag[BB];         // per-batch "ranks ready" flag (reset by logits kernel)

// ---------------- Kernel 1: logits = x @ w + b  (one warp per TWO rows) ----------------
__global__ void logits_kernel(const float* __restrict__ x,
                              const float* __restrict__ w,
                              const float* __restrict__ bias) {
    // reset per-batch flags for this replay (stream-ordered before kernel 2)
    if (blockIdx.x == 0 && threadIdx.x < BB) g_flag[threadIdx.x] = 0;

    int warpsPerBlock = blockDim.x >> 5;
    int warpId = threadIdx.x >> 5;
    int lane   = threadIdx.x & 31;
    int pair = blockIdx.x * warpsPerBlock + warpId;
    int row0 = pair * 2;
    if (row0 >= NROWS) return;

    const float4* xr0 = reinterpret_cast<const float4*>(x) + (size_t)row0 * D4;
    const float4* xr1 = xr0 + D4;
    const float4* w4  = reinterpret_cast<const float4*>(w);

    float4 a0[6], a1[6], wv[6];
    #pragma unroll
    for (int k = 0; k < 6; k++) a0[k] = xr0[k*32 + lane];
    #pragma unroll
    for (int k = 0; k < 6; k++) a1[k] = xr1[k*32 + lane];
    #pragma unroll
    for (int k = 0; k < 6; k++) wv[k] = __ldg(&w4[k*32 + lane]);

    float acc0 = 0.f, acc1 = 0.f;
    #pragma unroll
    for (int k = 0; k < 6; k++) {
        acc0 = fmaf(a0[k].x, wv[k].x, acc0);
        acc0 = fmaf(a0[k].y, wv[k].y, acc0);
        acc0 = fmaf(a0[k].z, wv[k].z, acc0);
        acc0 = fmaf(a0[k].w, wv[k].w, acc0);
        acc1 = fmaf(a1[k].x, wv[k].x, acc1);
        acc1 = fmaf(a1[k].y, wv[k].y, acc1);
        acc1 = fmaf(a1[k].z, wv[k].z, acc1);
        acc1 = fmaf(a1[k].w, wv[k].w, acc1);
    }
    #pragma unroll
    for (int off = 16; off; off >>= 1) {
        acc0 += __shfl_xor_sync(0xffffffffu, acc0, off);
        acc1 += __shfl_xor_sync(0xffffffffu, acc1, off);
    }
    if (lane == 0) {
        float bv = bias[0];
        g_logits[row0]     = acc0 + bv;
        g_logits[row0 + 1] = acc1 + bv;
    }
}

// ---------------- Kernel 2: fused rank + scatter + summary ----------------
// Blocks [0, BB)        : rank+softmax for batch b -> release flag -> summary (MLP-8)
// Blocks [BB, BB+NSCAT) : front-issue 8 x-row loads, spin on batch flag(s), store
__global__ void __launch_bounds__(NTHR)
gate_move_kernel(const float* __restrict__ x, float* __restrict__ out) {
    const float4* xin = reinterpret_cast<const float4*>(x);
    float4* o4 = reinterpret_cast<float4*>(out);
    const size_t skipBase = (size_t)BB * DENS * D4;
    const size_t sumBase  = (size_t)BB * (DENS + NSKIP) * D4;
    int tid = threadIdx.x;              // 0..191

    if (blockIdx.x < BB) {
        // ======== rank + softmax + summary for batch b ========
        __shared__ float s[TT];
        __shared__ float skipP[64];     // padded
        __shared__ float skipE[NSKIP];
        __shared__ int   sidx[64];      // padded
        __shared__ float swgt[64];      // padded

        int b = blockIdx.x;
        for (int i = tid; i < TT; i += NTHR) s[i] = g_logits[b*TT + i];
        if (tid < 64) { sidx[tid] = 0; swgt[tid] = 0.f; }   // pad defaults
        __syncthreads();

        for (int i = tid; i < TT; i += NTHR) {
            float my = s[i];
            int rank = 0;
            #pragma unroll 8
            for (int j = 0; j < TT; j++) {
                float v = s[j];
                rank += (v > my) || (v == my && j < i);   // stable: lower index wins
            }
            g_rank[b*TT + i] = rank;
            if (rank >= DENS) {
                int pos = (TT - 1) - rank;                // ascending skipped order
                sidx[pos] = i;
                skipP[pos] = 1.f / (1.f + expf(-my));     // sigmoid prob
            }
        }
        __syncthreads();

        // release scatter blocks ASAP (ranks are final)
        if (tid == 0) {
            __threadfence();
            atomicExch(&g_flag[b], 1);
        }

        // softmax over skipped probs
        if (tid < NSKIP) {
            float m = -1e30f;
            #pragma unroll
            for (int j = 0; j < NSKIP; j++) m = fmaxf(m, skipP[j]);
            skipE[tid] = expf(skipP[tid] - m);
        }
        __syncthreads();
        if (tid < NSKIP) {
            float sum = 0.f;
            #pragma unroll
            for (int j = 0; j < NSKIP; j++) sum += skipE[j];
            swgt[tid] = skipE[tid] / sum;
        }
        __syncthreads();

        // summary: 8 groups of 8 front-batched loads (MLP=8), padded entries weight 0
        float4 acc = make_float4(0.f, 0.f, 0.f, 0.f);
        #pragma unroll
        for (int g = 0; g < 64; g += 8) {
            float4 vv[8];
            #pragma unroll
            for (int j = 0; j < 8; j++)
                vv[j] = xin[((size_t)b*TT + sidx[g+j]) * D4 + tid];
            #pragma unroll
            for (int j = 0; j < 8; j++) {
                float wgt = swgt[g+j];
                acc.x = fmaf(wgt, vv[j].x, acc.x);
                acc.y = fmaf(wgt, vv[j].y, acc.y);
                acc.z = fmaf(wgt, vv[j].z, acc.z);
                acc.w = fmaf(wgt, vv[j].w, acc.w);
            }
        }
        o4[sumBase + (size_t)b * D4 + tid] = acc;
    } else {
        // ======== scatter: loads first, then wait for ranks, then store ========
        int sb = (NSCAT - 1) - ((int)blockIdx.x - BB);  // reversed: freshest L2 lines first
        int base = sb * RPB;

        // Front-batched independent streaming loads (in flight during rank wait)
        float4 v[RPB];
        #pragma unroll
        for (int r = 0; r < RPB; r++)
            v[r] = __ldcs(&xin[((size_t)(base + r)) * D4 + tid]);

        int b0 = base / TT;
        int b1 = (base + RPB - 1) / TT;
        if (tid == 0) {
            while (atomicAdd(&g_flag[b0], 0) == 0) { }
            if (b1 != b0) while (atomicAdd(&g_flag[b1], 0) == 0) { }
        }
        __syncthreads();
        __threadfence();   // acquire: g_rank writes visible

        #pragma unroll
        for (int r = 0; r < RPB; r++) {
            int src = base + r;
            int b = src / TT;
            int rank = g_rank[src];
            size_t off = (rank < DENS)
                ? ((size_t)(b*DENS + rank) * D4)
                : (skipBase + (size_t)(b*NSKIP + ((TT-1) - rank)) * D4);
            __stcs(&o4[off + tid], v[r]);
        }
    }
}

extern "C" void kernel_launch(void* const* d_in, const int* in_sizes, int n_in,
                              void* d_out, int out_size) {
    const float* x    = (const float*)d_in[0];
    const float* w    = (const float*)d_in[1];
    const float* bias = (const float*)d_in[2];
    float* out = (float*)d_out;

    // 1) logits (+ flag reset): 2 rows/warp, 8 warps/block
    logits_kernel<<<(NROWS/2 + 7) / 8, 256>>>(x, w, bias);
    // 2) fused rank (blocks 0-63, wave-1 resident) + scatter + summary
    gate_move_kernel<<<BB + NSCAT, NTHR>>>(x, out);
}